// round 15
// baseline (speedup 1.0000x reference)
#include <cuda_runtime.h>
#include <math.h>

// Problem constants (fixed shapes from setup_inputs)
#define D 64
#define R 64
#define T 4096
#define B 8
#define NTOK (B * T)                  // 32768
#define STRENGTH 0.1f
#define SC 0.17677669529663687f       // sqrt(2/64)

#define K1_BLOCKS 128                 // 8 batches * 16 chunks of 256 tokens
#define K1_CHUNKS 16                  // per batch
#define STRIDE 68                     // smem row stride (floats): 16B-aligned

// dynamic smem layout (floats)
#define OFF_W   0                     // [128][68] combined weights (persistent)
#define OFF_C   (128 * STRIDE)        // [128][68] coords (per sub-pass)
#define OFF_P   (256 * STRIDE)        // [16][64]  per-token-group partials
#define OFF_B1  (OFF_P + 1024)        // [64]
#define OFF_W2  (OFF_B1 + 64)         // [64]
#define OFF_BR  (OFF_W2 + 64)         // [64]
#define SMEM_FLOATS (OFF_BR + 64)
#define SMEM_BYTES  (SMEM_FLOATS * 4) // 74496 B

// Scratch (device globals — no allocation)
__device__ float g_phi[(size_t)NTOK * R];        // 8 MB (L2-resident at use)
__device__ float g_partial[K1_BLOCKS * R];
__device__ float g_phisum[B * R];
__device__ unsigned g_done;                      // zero-initialized; self-resets

// ---------------------------------------------------------------------------
// K1: tiled GEMM coords @ [w1^T | W], 256 tokens/block, two sub-passes of 128.
// Thread tile: 8 tokens (tg) x 8 rows (rg + 16*i; i<4 = w1, i>=4 = W).
// 64 independent accumulators -> high ILP at low occupancy.
// Last-finishing block reduces all chunk partials -> g_phisum (deterministic).
// ---------------------------------------------------------------------------
__global__ __launch_bounds__(256) void k1_phi_mass(
    const float* __restrict__ coords, const float* __restrict__ w1,
    const float* __restrict__ b1, const float* __restrict__ w2,
    const float* __restrict__ b2, const float* __restrict__ W,
    const float* __restrict__ bR)
{
    extern __shared__ float sm[];
    float* s_w    = sm + OFF_W;
    float* s_c    = sm + OFF_C;
    float* s_part = sm + OFF_P;
    float* s_b1   = sm + OFF_B1;
    float* s_w2   = sm + OFF_W2;
    float* s_bR   = sm + OFF_BR;
    __shared__ bool s_last;

    const int tid = threadIdx.x;
    const int bb = blockIdx.x >> 4, chunk = blockIdx.x & 15;
    const int tokBase0 = bb * T + chunk * 256;

    // --- stage weights (float4 where layout permits) ---
    {
        const float4* w1f4 = (const float4*)w1;
        for (int idx = tid; idx < 1024; idx += 256) {
            int r = idx >> 4, k4i = idx & 15;
            *(float4*)(s_w + r * STRIDE + k4i * 4) = w1f4[idx];
        }
        for (int idx = tid; idx < 4096; idx += 256) {   // W transpose: scalar
            int k = idx >> 6, r = idx & 63;
            s_w[(64 + r) * STRIDE + k] = W[idx];
        }
    }
    if (tid < 64) { s_b1[tid] = b1[tid]; s_w2[tid] = w2[tid]; s_bR[tid] = bR[tid]; }

    const int tg = tid >> 4;       // 0..15 : tokens tg*8 .. tg*8+7
    const int rg = tid & 15;       // 0..15 : rows rg + 16*i
    const float b2v = __ldg(b2);
    const float* cb = s_c + (tg * 8) * STRIDE;
    const float* wb = s_w + rg * STRIDE;

    float part[4] = {0.f, 0.f, 0.f, 0.f};

    for (int sub = 0; sub < 2; ++sub) {
        const int tokBase = tokBase0 + sub * 128;

        __syncthreads();
        {
            const float4* cf4 = (const float4*)(coords + (size_t)tokBase * D);
            for (int idx = tid; idx < 2048; idx += 256) {
                int t = idx >> 4, k4i = idx & 15;
                *(float4*)(s_c + t * STRIDE + k4i * 4) = cf4[idx];
            }
        }
        __syncthreads();

        float acc[8][8];
        #pragma unroll
        for (int j = 0; j < 8; ++j)
            #pragma unroll
            for (int i = 0; i < 8; ++i) acc[j][i] = 0.f;

        #pragma unroll 2
        for (int k4 = 0; k4 < 16; ++k4) {
            float4 w[8];
            #pragma unroll
            for (int i = 0; i < 8; ++i)
                w[i] = *(const float4*)(wb + i * 16 * STRIDE + k4 * 4);
            #pragma unroll
            for (int j = 0; j < 8; ++j) {
                const float4 c = *(const float4*)(cb + j * STRIDE + k4 * 4);
                #pragma unroll
                for (int i = 0; i < 8; ++i) {
                    acc[j][i] = fmaf(c.x, w[i].x, acc[j][i]);
                    acc[j][i] = fmaf(c.y, w[i].y, acc[j][i]);
                    acc[j][i] = fmaf(c.z, w[i].z, acc[j][i]);
                    acc[j][i] = fmaf(c.w, w[i].w, acc[j][i]);
                }
            }
        }

        // --- epilogue (registers + shfl only) ---
        #pragma unroll
        for (int j = 0; j < 8; ++j) {
            float mp = 0.f;
            #pragma unroll
            for (int i = 0; i < 4; ++i) {
                const int row = rg + i * 16;
                const float h = fmaxf(acc[j][i] + s_b1[row], 0.f);
                mp = fmaf(h, s_w2[row], mp);
            }
            mp += __shfl_xor_sync(0xffffffffu, mp, 8);
            mp += __shfl_xor_sync(0xffffffffu, mp, 4);
            mp += __shfl_xor_sync(0xffffffffu, mp, 2);
            mp += __shfl_xor_sync(0xffffffffu, mp, 1);
            const float x = mp + b2v;
            const float mass = fmaxf(x, 0.f) + __logf(1.f + __expf(-fabsf(x)));

            const size_t gbase = (size_t)(tokBase + tg * 8 + j) * R;
            #pragma unroll
            for (int i = 0; i < 4; ++i) {
                const int row = rg + i * 16;
                const float ph = SC * __cosf(acc[j][i + 4] + s_bR[row]);
                g_phi[gbase + row] = ph;
                part[i] = fmaf(mass, ph, part[i]);
            }
        }
    }

    __syncthreads();
    #pragma unroll
    for (int i = 0; i < 4; ++i)
        s_part[tg * 64 + rg + i * 16] = part[i];
    __syncthreads();

    if (tid < 64) {
        float s = 0.f;
        #pragma unroll
        for (int t = 0; t < 16; ++t) s += s_part[t * 64 + tid];
        g_partial[blockIdx.x * 64 + tid] = s;
    }

    // --- last block reduces partials -> phisum (deterministic fixed order) ---
    __threadfence();
    if (tid == 0)
        s_last = (atomicAdd(&g_done, 1u) == K1_BLOCKS - 1);
    __syncthreads();
    if (s_last) {
        for (int half = 0; half < 2; ++half) {
            const int b = half * 4 + (tid >> 6);
            const int r = tid & 63;
            float s = 0.f;
            #pragma unroll
            for (int c = 0; c < K1_CHUNKS; ++c)
                s += g_partial[(b * K1_CHUNKS + c) * 64 + r];
            g_phisum[b * 64 + r] = s;
        }
        if (tid == 0) g_done = 0;     // reset for next graph replay
    }
}

// ---------------------------------------------------------------------------
// K4: full-line 1 GiB stream of G with fused grav + diagonal add.
// Per-warp grav reduce; no __syncthreads. (Verified at 85.8% DRAM.)
// ---------------------------------------------------------------------------
__global__ __launch_bounds__(256) void k4_copy(const float4* __restrict__ G4,
                                               float4* __restrict__ O4)
{
    const unsigned tile = blockIdx.x;
    const size_t base = (size_t)tile * 1024;
    const unsigned t = threadIdx.x;
    const int lane = (int)(t & 31u);

    float4 v[4];
    #pragma unroll
    for (int k = 0; k < 4; ++k)
        v[k] = __ldcs(G4 + base + k * 256u + t);

    const unsigned bb = tile >> 12;                    // 4096 tiles per batch
    const float* ph = g_phi + (size_t)tile * R;
    const float* ps = g_phisum + bb * 64;
    float x = fmaf(ph[lane], ps[lane], ph[lane + 32] * ps[lane + 32]);
    x += __shfl_xor_sync(0xffffffffu, x, 16);
    x += __shfl_xor_sync(0xffffffffu, x, 8);
    x += __shfl_xor_sync(0xffffffffu, x, 4);
    x += __shfl_xor_sync(0xffffffffu, x, 2);
    x += __shfl_xor_sync(0xffffffffu, x, 1);
    const float gv = STRENGTH * x;                     // warp-uniform

    #pragma unroll
    for (int k = 0; k < 4; ++k) {
        const unsigned within = k * 256u + t;
        const int i  = (int)(within >> 4);
        const int j0 = (int)((within & 15u) << 2);
        const int d  = i - j0;
        if ((unsigned)d < 4u) {
            if      (d == 0) v[k].x += gv;
            else if (d == 1) v[k].y += gv;
            else if (d == 2) v[k].z += gv;
            else             v[k].w += gv;
        }
        __stcs(O4 + base + within, v[k]);
    }
}

// ---------------------------------------------------------------------------
extern "C" void kernel_launch(void* const* d_in, const int* in_sizes, int n_in,
                              void* d_out, int out_size)
{
    const float* G      = (const float*)d_in[0];
    const float* coords = (const float*)d_in[1];
    const float* w1     = (const float*)d_in[2];
    const float* b1     = (const float*)d_in[3];
    const float* w2     = (const float*)d_in[4];
    const float* b2     = (const float*)d_in[5];
    const float* W      = (const float*)d_in[6];
    const float* bR     = (const float*)d_in[7];
    float* out = (float*)d_out;

    cudaFuncSetAttribute(k1_phi_mass,
                         cudaFuncAttributeMaxDynamicSharedMemorySize, SMEM_BYTES);

    k1_phi_mass<<<K1_BLOCKS, 256, SMEM_BYTES>>>(coords, w1, b1, w2, b2, W, bR);
    k4_copy<<<NTOK, 256>>>((const float4*)G, (float4*)out);
}